// round 15
// baseline (speedup 1.0000x reference)
#include <cuda_runtime.h>
#include <math.h>

// Problem shape (fixed by the dataset)
#define B_    16
#define S_    8192
#define QDIM  1024
#define KDIM  256
#define FLOAT_MIN_V (-100000.0f)

#define CHUNKS 64
#define SCHUNK (S_ / CHUNKS)   // 128

// Scratch (no allocations allowed in kernel_launch)
__device__ float g_qp[B_ * KDIM];                    // projected query + bias, [B,K]
__device__ float g_partial[B_ * CHUNKS * KDIM];      // per-chunk normalized ctx partials
__device__ float g_lsum[B_ * CHUNKS];                // per-chunk sum of exp weights
__device__ unsigned int g_count[B_];                 // completed-chunk counters

// HW tanh (sm_75+): MUFU-class; measured output rel_err impact ~1.6e-6.
__device__ __forceinline__ float tanh_hw(float x)
{
    float y;
    asm("tanh.approx.f32 %0, %1;" : "=f"(y) : "f"(x));
    return y;
}

// ---------------------------------------------------------------------------
// Kernel 1: qp[b,k] = b_attr[k] + sum_q query[b,q] * W[k,q]
// one warp per (b,k); also re-zeroes the per-batch completion counters
// (stream order guarantees this lands before k_ctx reads them).
// ---------------------------------------------------------------------------
__global__ void k_proj(const float* __restrict__ query,
                       const float* __restrict__ W,
                       const float* __restrict__ bvec)
{
    if (blockIdx.x == 0 && threadIdx.x < B_)
        g_count[threadIdx.x] = 0u;

    int gw   = (blockIdx.x * blockDim.x + threadIdx.x) >> 5;
    int lane = threadIdx.x & 31;
    if (gw >= B_ * KDIM) return;
    int b = gw / KDIM;
    int k = gw % KDIM;

    const float4* qrow = (const float4*)(query + (size_t)b * QDIM);
    const float4* wrow = (const float4*)(W + (size_t)k * QDIM);

    float acc = 0.f;
#pragma unroll
    for (int j = 0; j < QDIM / (32 * 4); j++) {      // 8 iters
        float4 q4 = qrow[lane + j * 32];
        float4 w4 = wrow[lane + j * 32];
        acc += q4.x * w4.x + q4.y * w4.y + q4.z * w4.z + q4.w * w4.w;
    }
#pragma unroll
    for (int o = 16; o; o >>= 1) acc += __shfl_xor_sync(0xFFFFFFFFu, acc, o);
    if (lane == 0) g_qp[b * KDIM + k] = acc + bvec[k];
}

// ---------------------------------------------------------------------------
// Kernel 2: per (b, s-chunk): w_s = exp(mask*e + (1-mask)*MIN) for 128 rows
// (warp-per-16-rows, 2-row batched loads, 4 LDG.128 in flight per lane),
// written UNNORMALIZED to scores region; per-chunk lsum to g_lsum.
// No max-subtraction needed: |e| <= sum|V_attr| <= 16 -> exp in [e-16, e16].
// ---------------------------------------------------------------------------
__global__ void __launch_bounds__(256) k_energy(const float* __restrict__ keys,
                                                const float* __restrict__ mask,
                                                const float* __restrict__ Vvec,
                                                float* __restrict__ scores)
{
    int b = blockIdx.x / CHUNKS;
    int c = blockIdx.x % CHUNKS;
    int t = threadIdx.x;                 // 0..255
    int lane = t & 31;
    int wid  = t >> 5;                   // 0..7
    int s0 = c * SCHUNK;

    __shared__ float sw[SCHUNK];

    const float* qp = g_qp + b * KDIM;
    float4 qv0 = *(const float4*)(qp + lane * 4);
    float4 qv1 = *(const float4*)(qp + lane * 4 + 128);
    float4 vv0 = *(const float4*)(Vvec + lane * 4);
    float4 vv1 = *(const float4*)(Vvec + lane * 4 + 128);

    int rbase = wid * 16;
    const float* krow = keys + ((size_t)b * S_ + s0 + rbase) * KDIM;
#pragma unroll 2
    for (int i = 0; i < 16; i += 2) {
        const float* r0p = krow + (size_t)i * KDIM;
        const float* r1p = krow + (size_t)(i + 1) * KDIM;
        float4 k00 = *(const float4*)(r0p + lane * 4);
        float4 k01 = *(const float4*)(r0p + lane * 4 + 128);
        float4 k10 = *(const float4*)(r1p + lane * 4);
        float4 k11 = *(const float4*)(r1p + lane * 4 + 128);

        float e0 = 0.f, e1 = 0.f;
        e0 += tanh_hw(k00.x + qv0.x) * vv0.x;
        e0 += tanh_hw(k00.y + qv0.y) * vv0.y;
        e0 += tanh_hw(k00.z + qv0.z) * vv0.z;
        e0 += tanh_hw(k00.w + qv0.w) * vv0.w;
        e0 += tanh_hw(k01.x + qv1.x) * vv1.x;
        e0 += tanh_hw(k01.y + qv1.y) * vv1.y;
        e0 += tanh_hw(k01.z + qv1.z) * vv1.z;
        e0 += tanh_hw(k01.w + qv1.w) * vv1.w;

        e1 += tanh_hw(k10.x + qv0.x) * vv0.x;
        e1 += tanh_hw(k10.y + qv0.y) * vv0.y;
        e1 += tanh_hw(k10.z + qv0.z) * vv0.z;
        e1 += tanh_hw(k10.w + qv0.w) * vv0.w;
        e1 += tanh_hw(k11.x + qv1.x) * vv1.x;
        e1 += tanh_hw(k11.y + qv1.y) * vv1.y;
        e1 += tanh_hw(k11.z + qv1.z) * vv1.z;
        e1 += tanh_hw(k11.w + qv1.w) * vv1.w;

#pragma unroll
        for (int o = 16; o; o >>= 1) {
            e0 += __shfl_xor_sync(0xFFFFFFFFu, e0, o);
            e1 += __shfl_xor_sync(0xFFFFFFFFu, e1, o);
        }

        if (lane == 0) {
            size_t gs = (size_t)b * S_ + s0 + rbase + i;
            float m0 = mask[gs];
            float m1 = mask[gs + 1];
            float w0 = __expf(m0 * e0 + (1.0f - m0) * FLOAT_MIN_V);
            float w1 = __expf(m1 * e1 + (1.0f - m1) * FLOAT_MIN_V);
            sw[rbase + i]     = w0;
            sw[rbase + i + 1] = w1;
            scores[gs]     = w0;   // unnormalized; normalized by k_ctx
            scores[gs + 1] = w1;
        }
    }
    __syncthreads();

    if (wid == 0) {
        float lc = sw[lane] + sw[lane + 32] + sw[lane + 64] + sw[lane + 96];
#pragma unroll
        for (int o = 16; o; o >>= 1) lc += __shfl_xor_sync(0xFFFFFFFFu, lc, o);
        if (lane == 0) g_lsum[b * CHUNKS + c] = lc;
    }
}

// ---------------------------------------------------------------------------
// Kernel 3: per (b, s-chunk):
//   preamble (one sync): warp 0-3 load w tile; warp 4 reduces batch lsums.
//   Phase B: float4-column normalized ctx partials -> g_partial.
//   score rewrite after the loads (off the values stream's critical path).
//   LAST block per batch (threadfence + atomic counter) reduces the 64
//   partials -> ctx, replacing the separate k_finalize launch (measured
//   ~4.5us tail-kernel floor, 3 rounds in a row).
// ---------------------------------------------------------------------------
__global__ void __launch_bounds__(256) k_ctx(const float* __restrict__ values,
                                             float* __restrict__ scores,
                                             float* __restrict__ ctx)
{
    int b = blockIdx.x / CHUNKS;
    int c = blockIdx.x % CHUNKS;
    int t = threadIdx.x;                 // 0..255
    int lane = t & 31;
    int wid  = t >> 5;
    int s0 = c * SCHUNK;

    __shared__ float  sw[SCHUNK];
    __shared__ float  s_inv;
    __shared__ float4 red4[256];
    __shared__ int    s_islast;

    // concurrent preamble: sw tile (threads 0..127) + denom (warp 4)
    if (t < SCHUNK)
        sw[t] = scores[(size_t)b * S_ + s0 + t];
    if (wid == 4) {
        float lc = g_lsum[b * CHUNKS + lane] + g_lsum[b * CHUNKS + lane + 32];
#pragma unroll
        for (int o = 16; o; o >>= 1) lc += __shfl_xor_sync(0xFFFFFFFFu, lc, o);
        if (lane == 0) s_inv = 1.0f / lc;
    }
    __syncthreads();

    int col = t & 63;                    // float4 column within row
    int r0  = t >> 6;                    // 0..3 row phase
    const float4* vp = (const float4*)(values + ((size_t)b * S_ + s0) * KDIM) + col;

    float4 a0 = make_float4(0.f, 0.f, 0.f, 0.f);
    float4 a1 = make_float4(0.f, 0.f, 0.f, 0.f);
    float4 a2 = make_float4(0.f, 0.f, 0.f, 0.f);
    float4 a3 = make_float4(0.f, 0.f, 0.f, 0.f);

#pragma unroll 2
    for (int jj = 0; jj < 32; jj += 4) {
        int r_0 = r0 + (jj + 0) * 4;
        int r_1 = r0 + (jj + 1) * 4;
        int r_2 = r0 + (jj + 2) * 4;
        int r_3 = r0 + (jj + 3) * 4;
        float4 v0 = vp[(size_t)r_0 * (KDIM / 4)];
        float4 v1 = vp[(size_t)r_1 * (KDIM / 4)];
        float4 v2 = vp[(size_t)r_2 * (KDIM / 4)];
        float4 v3 = vp[(size_t)r_3 * (KDIM / 4)];
        float s_0 = sw[r_0], s_1 = sw[r_1], s_2 = sw[r_2], s_3 = sw[r_3];
        a0.x += v0.x * s_0; a0.y += v0.y * s_0; a0.z += v0.z * s_0; a0.w += v0.w * s_0;
        a1.x += v1.x * s_1; a1.y += v1.y * s_1; a1.z += v1.z * s_1; a1.w += v1.w * s_1;
        a2.x += v2.x * s_2; a2.y += v2.y * s_2; a2.z += v2.z * s_2; a2.w += v2.w * s_2;
        a3.x += v3.x * s_3; a3.y += v3.y * s_3; a3.z += v3.z * s_3; a3.w += v3.w * s_3;
    }

    float inv = s_inv;

    // normalized scores -> d_out (after the loads, off the critical path)
    if (t < SCHUNK)
        scores[(size_t)b * S_ + s0 + t] = sw[t] * inv;

    float4 acc;
    acc.x = ((a0.x + a1.x) + (a2.x + a3.x)) * inv;
    acc.y = ((a0.y + a1.y) + (a2.y + a3.y)) * inv;
    acc.z = ((a0.z + a1.z) + (a2.z + a3.z)) * inv;
    acc.w = ((a0.w + a1.w) + (a2.w + a3.w)) * inv;
    red4[t] = acc;
    __syncthreads();

    if (t < 64) {
        float4 p0 = red4[t];
        float4 p1 = red4[t + 64];
        float4 p2 = red4[t + 128];
        float4 p3 = red4[t + 192];
        float4 r;
        r.x = (p0.x + p1.x) + (p2.x + p3.x);
        r.y = (p0.y + p1.y) + (p2.y + p3.y);
        r.z = (p0.z + p1.z) + (p2.z + p3.z);
        r.w = (p0.w + p1.w) + (p2.w + p3.w);
        ((float4*)(g_partial + ((size_t)b * CHUNKS + c) * KDIM))[t] = r;
    }

    // ---- last-block-done finalize (threadfence reduction pattern) ----
    __threadfence();                     // make this block's partial visible
    __syncthreads();                     // order all writers before the atomic
    if (t == 0) {
        unsigned int old = atomicAdd(&g_count[b], 1u);
        s_islast = (old == CHUNKS - 1);
    }
    __syncthreads();

    if (s_islast) {
        // fence again so subsequent reads observe all partials
        __threadfence();
        // 256 threads = 64 float4-cols x 4 chunk-groups; 16 LDG.128/thread,
        // all L2-resident; fixed summation order -> bitwise deterministic.
        int grp = t >> 6;                // chunk group 0..3
        const float4* pb = (const float4*)(g_partial + (size_t)b * CHUNKS * KDIM) + col;
        float4 acc2 = make_float4(0.f, 0.f, 0.f, 0.f);
#pragma unroll
        for (int i = 0; i < 16; i++) {
            float4 p = pb[(size_t)(grp * 16 + i) * (KDIM / 4)];
            acc2.x += p.x; acc2.y += p.y; acc2.z += p.z; acc2.w += p.w;
        }
        red4[t] = acc2;
        __syncthreads();
        if (t < 64) {
            float4 p0 = red4[t];
            float4 p1 = red4[t + 64];
            float4 p2 = red4[t + 128];
            float4 p3 = red4[t + 192];
            float4 r;
            r.x = (p0.x + p1.x) + (p2.x + p3.x);
            r.y = (p0.y + p1.y) + (p2.y + p3.y);
            r.z = (p0.z + p1.z) + (p2.z + p3.z);
            r.w = (p0.w + p1.w) + (p2.w + p3.w);
            ((float4*)(ctx + (size_t)b * KDIM))[t] = r;
        }
    }
}

// ---------------------------------------------------------------------------
// Launch
// inputs (metadata order): query, keys, values, kv_mask, W_attr, b_attr, V_attr
// output: [scores (B*S) | ctx (B*K)]
// ---------------------------------------------------------------------------
extern "C" void kernel_launch(void* const* d_in, const int* in_sizes, int n_in,
                              void* d_out, int out_size)
{
    const float* query = (const float*)d_in[0];
    const float* keys  = (const float*)d_in[1];
    const float* values= (const float*)d_in[2];
    const float* mask  = (const float*)d_in[3];
    const float* W     = (const float*)d_in[4];
    const float* bvec  = (const float*)d_in[5];
    const float* Vvec  = (const float*)d_in[6];

    float* out    = (float*)d_out;
    float* scores = out;                     // B*S
    float* ctx    = out + (size_t)B_ * S_;   // B*K

    // 1) query projection (+ counter reset)
    {
        int warps = B_ * KDIM;
        int blocks = (warps * 32 + 255) / 256;
        k_proj<<<blocks, 256>>>(query, W, bvec);
    }
    // 2) energies -> unnormalized exp weights + chunk sums
    k_energy<<<B_ * CHUNKS, 256>>>(keys, mask, Vvec, scores);
    // 3) normalized ctx partials + in-place score normalization
    //    + last-block-per-batch finalize -> ctx
    k_ctx<<<B_ * CHUNKS, 256>>>(values, scores, ctx);
}

// round 16
// speedup vs baseline: 1.1916x; 1.1916x over previous
#include <cuda_runtime.h>
#include <math.h>

// Problem shape (fixed by the dataset)
#define B_    16
#define S_    8192
#define QDIM  1024
#define KDIM  256
#define FLOAT_MIN_V (-100000.0f)

#define CHUNKS 64
#define SCHUNK (S_ / CHUNKS)   // 128

// Scratch (no allocations allowed in kernel_launch)
__device__ float g_qp[B_ * KDIM];                    // projected query + bias, [B,K]
__device__ float g_partial[B_ * CHUNKS * KDIM];      // per-chunk ctx partials

// HW tanh (sm_75+): MUFU-class; measured output rel_err impact ~1.6e-6.
__device__ __forceinline__ float tanh_hw(float x)
{
    float y;
    asm("tanh.approx.f32 %0, %1;" : "=f"(y) : "f"(x));
    return y;
}

// ---------------------------------------------------------------------------
// Kernel 1: qp[b,k] = b_attr[k] + sum_q query[b,q] * W[k,q]
// one warp per (b,k). Loads explicitly batched 4-deep per array
// (8 LDG.128 in flight) — previous version had regs=37 => MLP~2 and was
// DRAM-latency bound at 7.5us on the cold 1MB W read.
// ---------------------------------------------------------------------------
__global__ void k_proj(const float* __restrict__ query,
                       const float* __restrict__ W,
                       const float* __restrict__ bvec)
{
    int gw   = (blockIdx.x * blockDim.x + threadIdx.x) >> 5;
    int lane = threadIdx.x & 31;
    if (gw >= B_ * KDIM) return;
    int b = gw / KDIM;
    int k = gw % KDIM;

    const float4* qrow = (const float4*)(query + (size_t)b * QDIM);
    const float4* wrow = (const float4*)(W + (size_t)k * QDIM);

    float acc0 = 0.f, acc1 = 0.f, acc2 = 0.f, acc3 = 0.f;
#pragma unroll
    for (int j = 0; j < 2; j++) {
        // 8 independent LDG.128 issued before any FMA
        float4 w0 = wrow[lane + (j * 4 + 0) * 32];
        float4 w1 = wrow[lane + (j * 4 + 1) * 32];
        float4 w2 = wrow[lane + (j * 4 + 2) * 32];
        float4 w3 = wrow[lane + (j * 4 + 3) * 32];
        float4 q0 = qrow[lane + (j * 4 + 0) * 32];
        float4 q1 = qrow[lane + (j * 4 + 1) * 32];
        float4 q2 = qrow[lane + (j * 4 + 2) * 32];
        float4 q3 = qrow[lane + (j * 4 + 3) * 32];
        acc0 += q0.x * w0.x + q0.y * w0.y + q0.z * w0.z + q0.w * w0.w;
        acc1 += q1.x * w1.x + q1.y * w1.y + q1.z * w1.z + q1.w * w1.w;
        acc2 += q2.x * w2.x + q2.y * w2.y + q2.z * w2.z + q2.w * w2.w;
        acc3 += q3.x * w3.x + q3.y * w3.y + q3.z * w3.z + q3.w * w3.w;
    }
    float acc = (acc0 + acc1) + (acc2 + acc3);
#pragma unroll
    for (int o = 16; o; o >>= 1) acc += __shfl_xor_sync(0xFFFFFFFFu, acc, o);
    if (lane == 0) g_qp[b * KDIM + k] = acc + bvec[k];
}

// ---------------------------------------------------------------------------
// Kernel 2: energies[b,s] = mask*dot(tanh(keys[b,s,:]+qp[b,:]), V) + (1-mask)*MIN
// one warp per (b,s) row; K=256 -> 2 float4 loads per lane; HW tanh.
// (r7 best-measured shape)
// ---------------------------------------------------------------------------
__global__ void k_energy(const float* __restrict__ keys,
                         const float* __restrict__ mask,
                         const float* __restrict__ Vvec,
                         float* __restrict__ energies)
{
    int gw   = (blockIdx.x * blockDim.x + threadIdx.x) >> 5;
    int lane = threadIdx.x & 31;
    if (gw >= B_ * S_) return;
    int b = gw / S_;

    const float* row = keys + (size_t)gw * KDIM;
    const float* qp  = g_qp + b * KDIM;

    float4 kv0 = *(const float4*)(row + lane * 4);
    float4 kv1 = *(const float4*)(row + lane * 4 + 128);
    float4 qv0 = *(const float4*)(qp + lane * 4);
    float4 qv1 = *(const float4*)(qp + lane * 4 + 128);
    float4 vv0 = *(const float4*)(Vvec + lane * 4);
    float4 vv1 = *(const float4*)(Vvec + lane * 4 + 128);

    float acc = 0.f;
    acc += tanh_hw(kv0.x + qv0.x) * vv0.x;
    acc += tanh_hw(kv0.y + qv0.y) * vv0.y;
    acc += tanh_hw(kv0.z + qv0.z) * vv0.z;
    acc += tanh_hw(kv0.w + qv0.w) * vv0.w;
    acc += tanh_hw(kv1.x + qv1.x) * vv1.x;
    acc += tanh_hw(kv1.y + qv1.y) * vv1.y;
    acc += tanh_hw(kv1.z + qv1.z) * vv1.z;
    acc += tanh_hw(kv1.w + qv1.w) * vv1.w;

#pragma unroll
    for (int o = 16; o; o >>= 1) acc += __shfl_xor_sync(0xFFFFFFFFu, acc, o);

    if (lane == 0) {
        float m = mask[gw];
        energies[gw] = m * acc + (1.0f - m) * FLOAT_MIN_V;
    }
}

// ---------------------------------------------------------------------------
// Kernel 3: in-place softmax over S per batch. One block of 1024 per batch,
// 8 elements per thread. (r7 shape)
// ---------------------------------------------------------------------------
__global__ void k_softmax(float* __restrict__ scores)
{
    __shared__ float red[32];
    int b   = blockIdx.x;
    int tid = threadIdx.x;
    float* e = scores + (size_t)b * S_;

    float v[8];
    float mx = -INFINITY;
#pragma unroll
    for (int i = 0; i < 8; i++) {
        v[i] = e[tid + i * 1024];
        mx = fmaxf(mx, v[i]);
    }
#pragma unroll
    for (int o = 16; o; o >>= 1) mx = fmaxf(mx, __shfl_xor_sync(0xFFFFFFFFu, mx, o));
    if ((tid & 31) == 0) red[tid >> 5] = mx;
    __syncthreads();
    if (tid < 32) {
        float t = red[tid];
#pragma unroll
        for (int o = 16; o; o >>= 1) t = fmaxf(t, __shfl_xor_sync(0xFFFFFFFFu, t, o));
        red[tid] = t;
    }
    __syncthreads();
    mx = red[0];

    float sum = 0.f;
#pragma unroll
    for (int i = 0; i < 8; i++) {
        v[i] = __expf(v[i] - mx);
        sum += v[i];
    }
    __syncthreads();
#pragma unroll
    for (int o = 16; o; o >>= 1) sum += __shfl_xor_sync(0xFFFFFFFFu, sum, o);
    if ((tid & 31) == 0) red[tid >> 5] = sum;
    __syncthreads();
    if (tid < 32) {
        float t = red[tid];
#pragma unroll
        for (int o = 16; o; o >>= 1) t += __shfl_xor_sync(0xFFFFFFFFu, t, o);
        red[tid] = t;
    }
    __syncthreads();
    float inv = 1.0f / red[0];

#pragma unroll
    for (int i = 0; i < 8; i++) e[tid + i * 1024] = v[i] * inv;
}

// ---------------------------------------------------------------------------
// Kernel 4: ctx partials, float4 edition (r7 best-measured 68% DRAM shape).
// Thread t owns float4-column (t&63), rows (t>>6)+4j; 8 LDG.128 in flight.
// ---------------------------------------------------------------------------
__global__ void k_ctx_partial(const float* __restrict__ values,
                              const float* __restrict__ scores)
{
    int b = blockIdx.x / CHUNKS;
    int c = blockIdx.x % CHUNKS;
    int t = threadIdx.x;                 // 0..255
    int col = t & 63;
    int r0  = t >> 6;
    int s0 = c * SCHUNK;

    __shared__ float sc[SCHUNK];
    __shared__ float4 red4[256];

    if (t < SCHUNK)
        sc[t] = scores[(size_t)b * S_ + s0 + t];
    __syncthreads();

    const float4* vp = (const float4*)(values + ((size_t)b * S_ + s0) * KDIM) + col;

    float4 a0 = make_float4(0.f, 0.f, 0.f, 0.f);
    float4 a1 = make_float4(0.f, 0.f, 0.f, 0.f);
    float4 a2 = make_float4(0.f, 0.f, 0.f, 0.f);
    float4 a3 = make_float4(0.f, 0.f, 0.f, 0.f);

#pragma unroll 2
    for (int jj = 0; jj < 32; jj += 4) {
        int r_0 = r0 + (jj + 0) * 4;
        int r_1 = r0 + (jj + 1) * 4;
        int r_2 = r0 + (jj + 2) * 4;
        int r_3 = r0 + (jj + 3) * 4;
        float4 v0 = vp[(size_t)r_0 * (KDIM / 4)];
        float4 v1 = vp[(size_t)r_1 * (KDIM / 4)];
        float4 v2 = vp[(size_t)r_2 * (KDIM / 4)];
        float4 v3 = vp[(size_t)r_3 * (KDIM / 4)];
        float s_0 = sc[r_0], s_1 = sc[r_1], s_2 = sc[r_2], s_3 = sc[r_3];
        a0.x += v0.x * s_0; a0.y += v0.y * s_0; a0.z += v0.z * s_0; a0.w += v0.w * s_0;
        a1.x += v1.x * s_1; a1.y += v1.y * s_1; a1.z += v1.z * s_1; a1.w += v1.w * s_1;
        a2.x += v2.x * s_2; a2.y += v2.y * s_2; a2.z += v2.z * s_2; a2.w += v2.w * s_2;
        a3.x += v3.x * s_3; a3.y += v3.y * s_3; a3.z += v3.z * s_3; a3.w += v3.w * s_3;
    }

    float4 acc;
    acc.x = (a0.x + a1.x) + (a2.x + a3.x);
    acc.y = (a0.y + a1.y) + (a2.y + a3.y);
    acc.z = (a0.z + a1.z) + (a2.z + a3.z);
    acc.w = (a0.w + a1.w) + (a2.w + a3.w);

    red4[t] = acc;
    __syncthreads();

    if (t < 64) {
        float4 p0 = red4[t];
        float4 p1 = red4[t + 64];
        float4 p2 = red4[t + 128];
        float4 p3 = red4[t + 192];
        float4 r;
        r.x = (p0.x + p1.x) + (p2.x + p3.x);
        r.y = (p0.y + p1.y) + (p2.y + p3.y);
        r.z = (p0.z + p1.z) + (p2.z + p3.z);
        r.w = (p0.w + p1.w) + (p2.w + p3.w);
        ((float4*)(g_partial + ((size_t)b * CHUNKS + c) * KDIM))[t] = r;
    }
}

// ---------------------------------------------------------------------------
// Kernel 5: ctx[b,k] = sum_c partial — parallel version (measured 4.5us vs
// 5.4us serial). grid = B_*4; 256 threads = 64 k-cols x 4 chunk-groups.
// ---------------------------------------------------------------------------
__global__ void k_finalize(float* __restrict__ ctx)
{
    __shared__ float red[256];
    int b  = blockIdx.x >> 2;
    int kq = blockIdx.x & 3;
    int t  = threadIdx.x;                // 0..255
    int k  = kq * 64 + (t & 63);
    int g  = t >> 6;                     // chunk group 0..3

    const float* p = g_partial + (size_t)b * CHUNKS * KDIM + k;
    float acc = 0.f;
#pragma unroll
    for (int i = 0; i < 16; i++)
        acc += p[(size_t)(g * 16 + i) * KDIM];

    red[t] = acc;
    __syncthreads();
    if (t < 64)
        ctx[b * KDIM + kq * 64 + t] =
            (red[t] + red[t + 64]) + (red[t + 128] + red[t + 192]);
}

// ---------------------------------------------------------------------------
// Launch
// inputs (metadata order): query, keys, values, kv_mask, W_attr, b_attr, V_attr
// output: [scores (B*S) | ctx (B*K)]
// ---------------------------------------------------------------------------
extern "C" void kernel_launch(void* const* d_in, const int* in_sizes, int n_in,
                              void* d_out, int out_size)
{
    const float* query = (const float*)d_in[0];
    const float* keys  = (const float*)d_in[1];
    const float* values= (const float*)d_in[2];
    const float* mask  = (const float*)d_in[3];
    const float* W     = (const float*)d_in[4];
    const float* bvec  = (const float*)d_in[5];
    const float* Vvec  = (const float*)d_in[6];

    float* out    = (float*)d_out;
    float* scores = out;                     // B*S
    float* ctx    = out + (size_t)B_ * S_;   // B*K

    // 1) query projection
    {
        int warps = B_ * KDIM;
        int blocks = (warps * 32 + 255) / 256;
        k_proj<<<blocks, 256>>>(query, W, bvec);
    }
    // 2) energies
    {
        int warps = B_ * S_;
        int blocks = (warps * 32 + 255) / 256;
        k_energy<<<blocks, 256>>>(keys, mask, Vvec, scores);
    }
    // 3) softmax in place
    k_softmax<<<B_, 1024>>>(scores);
    // 4) ctx partials
    k_ctx_partial<<<B_ * CHUNKS, KDIM>>>(values, scores);
    // 5) parallel reduce
    k_finalize<<<B_ * 4, 256>>>(ctx);
}

// round 17
// speedup vs baseline: 1.2324x; 1.0342x over previous
#include <cuda_runtime.h>
#include <math.h>

// Problem shape (fixed by the dataset)
#define B_    16
#define S_    8192
#define QDIM  1024
#define KDIM  256
#define FLOAT_MIN_V (-100000.0f)

#define CHUNKS 64
#define SCHUNK (S_ / CHUNKS)   // 128

// Scratch (no allocations allowed in kernel_launch)
__device__ float g_qp[B_ * KDIM];                    // projected query + bias, [B,K]
__device__ float g_partial[B_ * CHUNKS * KDIM];      // per-chunk ctx partials
__device__ unsigned int g_count[B_];                 // completed-chunk counters

// HW tanh (sm_75+): MUFU-class; measured output rel_err impact ~1.6e-6.
__device__ __forceinline__ float tanh_hw(float x)
{
    float y;
    asm("tanh.approx.f32 %0, %1;" : "=f"(y) : "f"(x));
    return y;
}

// ---------------------------------------------------------------------------
// Kernel 1: qp[b,k] = b_attr[k] + sum_q query[b,q] * W[k,q]
// one warp per (b,k); 8 LDG.128 in flight. Block 0 also re-zeroes the
// per-batch completion counters (stream order puts this before k_ctx_partial).
// ---------------------------------------------------------------------------
__global__ void k_proj(const float* __restrict__ query,
                       const float* __restrict__ W,
                       const float* __restrict__ bvec)
{
    if (blockIdx.x == 0 && threadIdx.x < B_)
        g_count[threadIdx.x] = 0u;

    int gw   = (blockIdx.x * blockDim.x + threadIdx.x) >> 5;
    int lane = threadIdx.x & 31;
    if (gw >= B_ * KDIM) return;
    int b = gw / KDIM;
    int k = gw % KDIM;

    const float4* qrow = (const float4*)(query + (size_t)b * QDIM);
    const float4* wrow = (const float4*)(W + (size_t)k * QDIM);

    float acc0 = 0.f, acc1 = 0.f, acc2 = 0.f, acc3 = 0.f;
#pragma unroll
    for (int j = 0; j < 2; j++) {
        float4 w0 = wrow[lane + (j * 4 + 0) * 32];
        float4 w1 = wrow[lane + (j * 4 + 1) * 32];
        float4 w2 = wrow[lane + (j * 4 + 2) * 32];
        float4 w3 = wrow[lane + (j * 4 + 3) * 32];
        float4 q0 = qrow[lane + (j * 4 + 0) * 32];
        float4 q1 = qrow[lane + (j * 4 + 1) * 32];
        float4 q2 = qrow[lane + (j * 4 + 2) * 32];
        float4 q3 = qrow[lane + (j * 4 + 3) * 32];
        acc0 += q0.x * w0.x + q0.y * w0.y + q0.z * w0.z + q0.w * w0.w;
        acc1 += q1.x * w1.x + q1.y * w1.y + q1.z * w1.z + q1.w * w1.w;
        acc2 += q2.x * w2.x + q2.y * w2.y + q2.z * w2.z + q2.w * w2.w;
        acc3 += q3.x * w3.x + q3.y * w3.y + q3.z * w3.z + q3.w * w3.w;
    }
    float acc = (acc0 + acc1) + (acc2 + acc3);
#pragma unroll
    for (int o = 16; o; o >>= 1) acc += __shfl_xor_sync(0xFFFFFFFFu, acc, o);
    if (lane == 0) g_qp[b * KDIM + k] = acc + bvec[k];
}

// ---------------------------------------------------------------------------
// Kernel 2: energies[b,s] = mask*dot(tanh(keys[b,s,:]+qp[b,:]), V) + (1-mask)*MIN
// one warp per (b,s) row; K=256 -> 2 float4 loads per lane; HW tanh.
// ---------------------------------------------------------------------------
__global__ void k_energy(const float* __restrict__ keys,
                         const float* __restrict__ mask,
                         const float* __restrict__ Vvec,
                         float* __restrict__ energies)
{
    int gw   = (blockIdx.x * blockDim.x + threadIdx.x) >> 5;
    int lane = threadIdx.x & 31;
    if (gw >= B_ * S_) return;
    int b = gw / S_;

    const float* row = keys + (size_t)gw * KDIM;
    const float* qp  = g_qp + b * KDIM;

    float4 kv0 = *(const float4*)(row + lane * 4);
    float4 kv1 = *(const float4*)(row + lane * 4 + 128);
    float4 qv0 = *(const float4*)(qp + lane * 4);
    float4 qv1 = *(const float4*)(qp + lane * 4 + 128);
    float4 vv0 = *(const float4*)(Vvec + lane * 4);
    float4 vv1 = *(const float4*)(Vvec + lane * 4 + 128);

    float acc = 0.f;
    acc += tanh_hw(kv0.x + qv0.x) * vv0.x;
    acc += tanh_hw(kv0.y + qv0.y) * vv0.y;
    acc += tanh_hw(kv0.z + qv0.z) * vv0.z;
    acc += tanh_hw(kv0.w + qv0.w) * vv0.w;
    acc += tanh_hw(kv1.x + qv1.x) * vv1.x;
    acc += tanh_hw(kv1.y + qv1.y) * vv1.y;
    acc += tanh_hw(kv1.z + qv1.z) * vv1.z;
    acc += tanh_hw(kv1.w + qv1.w) * vv1.w;

#pragma unroll
    for (int o = 16; o; o >>= 1) acc += __shfl_xor_sync(0xFFFFFFFFu, acc, o);

    if (lane == 0) {
        float m = mask[gw];
        energies[gw] = m * acc + (1.0f - m) * FLOAT_MIN_V;
    }
}

// ---------------------------------------------------------------------------
// Kernel 3: in-place softmax over S per batch. One block of 1024 per batch.
// ---------------------------------------------------------------------------
__global__ void k_softmax(float* __restrict__ scores)
{
    __shared__ float red[32];
    int b   = blockIdx.x;
    int tid = threadIdx.x;
    float* e = scores + (size_t)b * S_;

    float v[8];
    float mx = -INFINITY;
#pragma unroll
    for (int i = 0; i < 8; i++) {
        v[i] = e[tid + i * 1024];
        mx = fmaxf(mx, v[i]);
    }
#pragma unroll
    for (int o = 16; o; o >>= 1) mx = fmaxf(mx, __shfl_xor_sync(0xFFFFFFFFu, mx, o));
    if ((tid & 31) == 0) red[tid >> 5] = mx;
    __syncthreads();
    if (tid < 32) {
        float t = red[tid];
#pragma unroll
        for (int o = 16; o; o >>= 1) t = fmaxf(t, __shfl_xor_sync(0xFFFFFFFFu, t, o));
        red[tid] = t;
    }
    __syncthreads();
    mx = red[0];

    float sum = 0.f;
#pragma unroll
    for (int i = 0; i < 8; i++) {
        v[i] = __expf(v[i] - mx);
        sum += v[i];
    }
    __syncthreads();
#pragma unroll
    for (int o = 16; o; o >>= 1) sum += __shfl_xor_sync(0xFFFFFFFFu, sum, o);
    if ((tid & 31) == 0) red[tid >> 5] = sum;
    __syncthreads();
    if (tid < 32) {
        float t = red[tid];
#pragma unroll
        for (int o = 16; o; o >>= 1) t += __shfl_xor_sync(0xFFFFFFFFu, t, o);
        red[tid] = t;
    }
    __syncthreads();
    float inv = 1.0f / red[0];

#pragma unroll
    for (int i = 0; i < 8; i++) e[tid + i * 1024] = v[i] * inv;
}

// ---------------------------------------------------------------------------
// Kernel 4: ctx partials (measured 71.7% DRAM shape) + last-block finalize
// via RELEASE/ACQUIRE scoped atomics — NO __threadfence in the hot path
// (r15's __threadfence emitted CCTL.IVALL = L1D flush in all 1024 blocks,
// +10us). Here: non-last blocks pay one atom.add.release.gpu on one thread;
// only the 16 last blocks execute fence.acq_rel.gpu + the 64-chunk reduce.
// Fixed summation order -> bitwise deterministic.
// ---------------------------------------------------------------------------
__global__ void __launch_bounds__(256) k_ctx_partial(const float* __restrict__ values,
                                                     const float* __restrict__ scores,
                                                     float* __restrict__ ctx)
{
    int b = blockIdx.x / CHUNKS;
    int c = blockIdx.x % CHUNKS;
    int t = threadIdx.x;                 // 0..255
    int col = t & 63;
    int r0  = t >> 6;
    int s0 = c * SCHUNK;

    __shared__ float sc[SCHUNK];
    __shared__ float4 red4[256];
    __shared__ int s_islast;

    if (t < SCHUNK)
        sc[t] = scores[(size_t)b * S_ + s0 + t];
    __syncthreads();

    const float4* vp = (const float4*)(values + ((size_t)b * S_ + s0) * KDIM) + col;

    float4 a0 = make_float4(0.f, 0.f, 0.f, 0.f);
    float4 a1 = make_float4(0.f, 0.f, 0.f, 0.f);
    float4 a2 = make_float4(0.f, 0.f, 0.f, 0.f);
    float4 a3 = make_float4(0.f, 0.f, 0.f, 0.f);

#pragma unroll 2
    for (int jj = 0; jj < 32; jj += 4) {
        int r_0 = r0 + (jj + 0) * 4;
        int r_1 = r0 + (jj + 1) * 4;
        int r_2 = r0 + (jj + 2) * 4;
        int r_3 = r0 + (jj + 3) * 4;
        float4 v0 = vp[(size_t)r_0 * (KDIM / 4)];
        float4 v1 = vp[(size_t)r_1 * (KDIM / 4)];
        float4 v2 = vp[(size_t)r_2 * (KDIM / 4)];
        float4 v3 = vp[(size_t)r_3 * (KDIM / 4)];
        float s_0 = sc[r_0], s_1 = sc[r_1], s_2 = sc[r_2], s_3 = sc[r_3];
        a0.x += v0.x * s_0; a0.y += v0.y * s_0; a0.z += v0.z * s_0; a0.w += v0.w * s_0;
        a1.x += v1.x * s_1; a1.y += v1.y * s_1; a1.z += v1.z * s_1; a1.w += v1.w * s_1;
        a2.x += v2.x * s_2; a2.y += v2.y * s_2; a2.z += v2.z * s_2; a2.w += v2.w * s_2;
        a3.x += v3.x * s_3; a3.y += v3.y * s_3; a3.z += v3.z * s_3; a3.w += v3.w * s_3;
    }

    float4 acc;
    acc.x = (a0.x + a1.x) + (a2.x + a3.x);
    acc.y = (a0.y + a1.y) + (a2.y + a3.y);
    acc.z = (a0.z + a1.z) + (a2.z + a3.z);
    acc.w = (a0.w + a1.w) + (a2.w + a3.w);

    red4[t] = acc;
    __syncthreads();

    if (t < 64) {
        float4 p0 = red4[t];
        float4 p1 = red4[t + 64];
        float4 p2 = red4[t + 128];
        float4 p3 = red4[t + 192];
        float4 r;
        r.x = (p0.x + p1.x) + (p2.x + p3.x);
        r.y = (p0.y + p1.y) + (p2.y + p3.y);
        r.z = (p0.z + p1.z) + (p2.z + p3.z);
        r.w = (p0.w + p1.w) + (p2.w + p3.w);
        ((float4*)(g_partial + ((size_t)b * CHUNKS + c) * KDIM))[t] = r;
    }
    __syncthreads();                     // partial writes ordered before atomic

    if (t == 0) {
        // release: makes this block's partial visible at gpu scope,
        // without flushing L1 (STRONG.GPU atomic, not CCTL.IVALL).
        unsigned int old;
        asm volatile("atom.add.release.gpu.u32 %0, [%1], 1;"
                     : "=r"(old) : "l"(&g_count[b]) : "memory");
        s_islast = (old == CHUNKS - 1);
    }
    __syncthreads();

    if (s_islast) {
        // acquire: only the 16 last blocks pay the full fence.
        asm volatile("fence.acq_rel.gpu;" ::: "memory");
        int grp = t >> 6;                // chunk group 0..3
        const float4* pb = (const float4*)(g_partial + (size_t)b * CHUNKS * KDIM) + col;
        float4 acc2 = make_float4(0.f, 0.f, 0.f, 0.f);
#pragma unroll
        for (int i = 0; i < 16; i++) {
            float4 p = pb[(size_t)(grp * 16 + i) * (KDIM / 4)];
            acc2.x += p.x; acc2.y += p.y; acc2.z += p.z; acc2.w += p.w;
        }
        red4[t] = acc2;
        __syncthreads();
        if (t < 64) {
            float4 p0 = red4[t];
            float4 p1 = red4[t + 64];
            float4 p2 = red4[t + 128];
            float4 p3 = red4[t + 192];
            float4 r;
            r.x = (p0.x + p1.x) + (p2.x + p3.x);
            r.y = (p0.y + p1.y) + (p2.y + p3.y);
            r.z = (p0.z + p1.z) + (p2.z + p3.z);
            r.w = (p0.w + p1.w) + (p2.w + p3.w);
            ((float4*)(ctx + (size_t)b * KDIM))[t] = r;
        }
    }
}

// ---------------------------------------------------------------------------
// Launch
// inputs (metadata order): query, keys, values, kv_mask, W_attr, b_attr, V_attr
// output: [scores (B*S) | ctx (B*K)]
// ---------------------------------------------------------------------------
extern "C" void kernel_launch(void* const* d_in, const int* in_sizes, int n_in,
                              void* d_out, int out_size)
{
    const float* query = (const float*)d_in[0];
    const float* keys  = (const float*)d_in[1];
    const float* values= (const float*)d_in[2];
    const float* mask  = (const float*)d_in[3];
    const float* W     = (const float*)d_in[4];
    const float* bvec  = (const float*)d_in[5];
    const float* Vvec  = (const float*)d_in[6];

    float* out    = (float*)d_out;
    float* scores = out;                     // B*S
    float* ctx    = out + (size_t)B_ * S_;   // B*K

    // 1) query projection (+ counter reset)
    {
        int warps = B_ * KDIM;
        int blocks = (warps * 32 + 255) / 256;
        k_proj<<<blocks, 256>>>(query, W, bvec);
    }
    // 2) energies
    {
        int warps = B_ * S_;
        int blocks = (warps * 32 + 255) / 256;
        k_energy<<<blocks, 256>>>(keys, mask, Vvec, scores);
    }
    // 3) softmax in place
    k_softmax<<<B_, 1024>>>(scores);
    // 4) ctx partials + last-block finalize -> ctx
    k_ctx_partial<<<B_ * CHUNKS, 256>>>(values, scores, ctx);
}